// round 8
// baseline (speedup 1.0000x reference)
#include <cuda_runtime.h>
#include <math.h>
#include <stdint.h>

#define T_LEN 1024
#define BATCH 32
#define DIN   256
#define HID   512
#define G4    2048
#define NB    128
#define NT    512
#define BH    (BATCH*HID)

__device__ float g_gx[(long)T_LEN * BATCH * G4];          // [T][B][4H]
__device__ float g_hs4[(long)T_LEN * NB * BATCH * 4];     // [T][blk][b][4]
__device__ unsigned g_cnt16[1024];                        // counters at sg*64

// ---------------------------------------------------------------- helpers
__device__ __forceinline__ float fast_tanh(float x) {
  float y; asm("tanh.approx.f32 %0, %1;" : "=f"(y) : "f"(x)); return y;
}
__device__ __forceinline__ float fast_sig(float x) {
  return 0.5f * fast_tanh(0.5f * x) + 0.5f;
}
__device__ __forceinline__ void fma2(unsigned long long& d,
                                     unsigned long long a, unsigned long long b) {
  asm("fma.rn.f32x2 %0, %1, %2, %0;" : "+l"(d) : "l"(a), "l"(b));
}
__device__ __forceinline__ float hsum2(unsigned long long v) {
  return __uint_as_float((unsigned)v) + __uint_as_float((unsigned)(v >> 32));
}

// ---------------- phase 1: gx = x^T @ W_ih^T + (b_ih + b_hh) ----------------
__global__ __launch_bounds__(256) void gemm_input(
    const float* __restrict__ x, const float* __restrict__ Wih,
    const float* __restrict__ bih, const float* __restrict__ bhh) {
  __shared__ float xs[32][68];
  __shared__ float wsT[32][68];
  const int t0 = blockIdx.x * 64, n0 = blockIdx.y * 64, b = blockIdx.z;
  const int tid = threadIdx.x;
  const int tt4 = tid & 15, nn4 = tid >> 4;

  float acc[4][4];
#pragma unroll
  for (int i = 0; i < 4; i++)
#pragma unroll
    for (int j = 0; j < 4; j++) acc[i][j] = 0.f;

  for (int d0 = 0; d0 < DIN; d0 += 32) {
#pragma unroll
    for (int r = 0; r < 32; r += 4) {
      int dd = r + (tid >> 6);
      int tt = tid & 63;
      xs[dd][tt] = x[((long)b * DIN + d0 + dd) * T_LEN + t0 + tt];
    }
#pragma unroll
    for (int r = 0; r < 64; r += 8) {
      int nn = r + (tid >> 5);
      int dd = tid & 31;
      wsT[dd][nn] = Wih[(long)(n0 + nn) * DIN + d0 + dd];
    }
    __syncthreads();
#pragma unroll
    for (int dd = 0; dd < 32; dd++) {
      float4 a = *(const float4*)&xs[dd][tt4 * 4];
      float4 w = *(const float4*)&wsT[dd][nn4 * 4];
      acc[0][0] += a.x * w.x; acc[0][1] += a.x * w.y; acc[0][2] += a.x * w.z; acc[0][3] += a.x * w.w;
      acc[1][0] += a.y * w.x; acc[1][1] += a.y * w.y; acc[1][2] += a.y * w.z; acc[1][3] += a.y * w.w;
      acc[2][0] += a.z * w.x; acc[2][1] += a.z * w.y; acc[2][2] += a.z * w.z; acc[2][3] += a.z * w.w;
      acc[3][0] += a.w * w.x; acc[3][1] += a.w * w.y; acc[3][2] += a.w * w.z; acc[3][3] += a.w * w.w;
    }
    __syncthreads();
  }
  const int n = n0 + nn4 * 4;
  float4 b1 = *(const float4*)&bih[n];
  float4 b2 = *(const float4*)&bhh[n];
  float4 bv = make_float4(b1.x + b2.x, b1.y + b2.y, b1.z + b2.z, b1.w + b2.w);
#pragma unroll
  for (int i = 0; i < 4; i++) {
    int t = t0 + tt4 * 4 + i;
    float4 o = make_float4(acc[i][0] + bv.x, acc[i][1] + bv.y,
                           acc[i][2] + bv.z, acc[i][3] + bv.w);
    *(float4*)&g_gx[(long)t * (BATCH * G4) + (long)b * G4 + n] = o;
  }
}

__global__ void init_bar() {
  if (threadIdx.x < 16) *(volatile unsigned*)&g_cnt16[threadIdx.x * 64] = 0u;
}

__global__ void dummy_k() {}

// ---------------- phase 2: persistent recurrent scan (sub-chunk pipeline) ---
// 128 blocks x 512 threads. Block owns units j = blk*4+{0..3} (16 W rows in
// SMEM). Warp wid: q = wid>>2 (k-chunk), s = wid&3 (home sub-chunk);
// bh = wid&1, gh = (wid>>1)&1 select batch/gate halves for compute.
// h interchange: g_hs4[t][blk][b][4]; sub-chunk w = 8 producer blocks = 4KB,
// fetched by warp w's own cp.async.bulk gated by counter w (32 warp-arrivals)
// into hsm[w*1024], completion mbar[w]. Compute consumes sub-chunks of its
// chunk q in rotated order starting at its own s (order-independent accum).
#define KW      516
#define SM_W    (16 * KW)              // 8256
#define SM_H    (16 * 1024)            // 16384
#define SM_RED  (64 * 33)              // 2112 (x2 ping-pong)
#define SM_GXS  (16 * 33)              // 528  (x2 ping-pong)
#define SMEM_SCAN_FLOATS (SM_W + SM_H + 2 * SM_RED + 2 * SM_GXS + 40)
#define SMEM_SCAN_BYTES  (SMEM_SCAN_FLOATS * 4)

__global__ __launch_bounds__(NT, 1) void lstm_scan(const float* __restrict__ Whh) {
  extern __shared__ float sm[];
  float* Wsm  = sm;
  float* hsm  = Wsm + SM_W;
  float* red2 = hsm + SM_H;                 // [2][2112]
  float* gxs2 = red2 + 2 * SM_RED;          // [2][528]
  unsigned long long* mbar = (unsigned long long*)(gxs2 + 2 * SM_GXS);  // 16

  const int tid = threadIdx.x, blk = blockIdx.x;
  const int wid = tid >> 5, lane = tid & 31;
  const int bh = wid & 1, gh = (wid >> 1) & 1;
  const int q = wid >> 2, s = wid & 3;
  const int rsub = lane & 3, bsub = lane >> 2;
  const int r0 = gh * 8 + rsub * 2;
  const int b0 = bh * 16 + bsub * 2;
  const uint32_t mb_base = (uint32_t)__cvta_generic_to_shared(mbar);

  // persistent W_hh slice: row r = g*4+jj  <-  W_hh[g*512 + blk*4 + jj][:]
  for (int idx = tid; idx < 16 * HID; idx += NT) {
    int r = idx >> 9, k = idx & 511;
    int g = r >> 2, jj = r & 3;
    Wsm[r * KW + k] = Whh[(long)(g * HID + blk * 4 + jj) * HID + k];
  }
  for (int i = tid; i < SM_H; i += NT) hsm[i] = 0.f;
  if (tid < 16)
    asm volatile("mbarrier.init.shared.b64 [%0], 1;" :: "r"(mb_base + tid * 8));
  __syncthreads();

  const ulonglong2* w0p = (const ulonglong2*)(Wsm + r0 * KW + q * 128);
  const ulonglong2* w1p = (const ulonglong2*)(Wsm + (r0 + 1) * KW + q * 128);

  const int rb_j = tid >> 5, rb_b = tid & 31;   // reducer mapping (tid<128)
  float c_reg = 0.f;

  for (int t = 0; t < T_LEN; t++) {
    float* redb = red2 + (t & 1) * SM_RED;
    float* gxsb = gxs2 + (t & 1) * SM_GXS;

    // ---- gx prefetch (regs, independent of h) ----
    float4 gxv;
    if (tid < 128) {
      int b = tid >> 2, g = tid & 3;
      gxv = *(const float4*)&g_gx[(long)t * (BATCH * G4) + (long)b * G4 + g * HID + blk * 4];
    }

    // ---- sub-chunk fetch: every warp's lane 0 polls its own counter ----
    if (t > 0 && lane == 0) {
      const unsigned tgt = 32u * (unsigned)t;
      unsigned v;
      do {
        asm volatile("ld.acquire.gpu.global.u32 %0, [%1];"
                     : "=r"(v) : "l"(&g_cnt16[wid * 64]));
      } while (v < tgt);
      asm volatile("fence.proxy.async;" ::: "memory");
      uint32_t mb = mb_base + wid * 8;
      asm volatile("mbarrier.arrive.expect_tx.shared.b64 _, [%0], %1;"
                   :: "r"(mb), "r"(4096u));
      const float* src = g_hs4 + ((long)(t - 1) * NB + wid * 8) * (BATCH * 4);
      uint32_t d32 = (uint32_t)__cvta_generic_to_shared(hsm + wid * 1024);
      asm volatile(
        "cp.async.bulk.shared::cluster.global.mbarrier::complete_tx::bytes "
        "[%0], [%1], %2, [%3];"
        :: "r"(d32), "l"(src), "r"(4096u), "r"(mb) : "memory");
    }
    // gx -> smem transposed (ping-pong buffer)
    if (tid < 128) {
      int b = tid >> 2, g = tid & 3;
      gxsb[(g * 4 + 0) * 33 + b] = gxv.x;
      gxsb[(g * 4 + 1) * 33 + b] = gxv.y;
      gxsb[(g * 4 + 2) * 33 + b] = gxv.z;
      gxsb[(g * 4 + 3) * 33 + b] = gxv.w;
    }

    // ---- f32x2 GEMM partial over 4 sub-rounds (rotated, own sub first) ----
    unsigned long long a00 = 0ull, a01 = 0ull, a10 = 0ull, a11 = 0ull;
#pragma unroll
    for (int r = 0; r < 4; r++) {
      const int sr = (s + r) & 3;
      if (t > 0) {
        uint32_t mb = mb_base + (q * 4 + sr) * 8;
        uint32_t done = 0;
        unsigned phase = (unsigned)((t - 1) & 1);
        while (!done) {
          asm volatile(
            "{\n\t.reg .pred p;\n\t"
            "mbarrier.try_wait.parity.shared.b64 p, [%1], %2, 10000000;\n\t"
            "selp.b32 %0, 1, 0, p;\n\t}"
            : "=r"(done) : "r"(mb), "r"(phase) : "memory");
        }
      }
      const float* hb = hsm + (q * 4 + sr) * 1024 + b0 * 4;
#pragma unroll
      for (int i = 0; i < 8; i++) {
        ulonglong2 wa = w0p[sr * 8 + i];
        ulonglong2 wb = w1p[sr * 8 + i];
        ulonglong2 ha  = *(const ulonglong2*)(hb + i * 128);
        ulonglong2 hbv = *(const ulonglong2*)(hb + i * 128 + 4);
        fma2(a00, wa.x, ha.x);  fma2(a00, wa.y, ha.y);
        fma2(a01, wa.x, hbv.x); fma2(a01, wa.y, hbv.y);
        fma2(a10, wb.x, ha.x);  fma2(a10, wb.y, ha.y);
        fma2(a11, wb.x, hbv.x); fma2(a11, wb.y, hbv.y);
      }
    }
    {
      float* rp = redb + (q * 16 + r0) * 33;
      rp[b0]          = hsum2(a00);
      rp[b0 + 1]      = hsum2(a01);
      rp[33 + b0]     = hsum2(a10);
      rp[33 + b0 + 1] = hsum2(a11);
    }
    __syncthreads();

    // ---- reduce + gates (tid<128 owns (j = blk*4 + rb_j, b = rb_b)) ----
    if (tid < 128) {
      float s0 = gxsb[(0 * 4 + rb_j) * 33 + rb_b];
      float s1 = gxsb[(1 * 4 + rb_j) * 33 + rb_b];
      float s2 = gxsb[(2 * 4 + rb_j) * 33 + rb_b];
      float s3 = gxsb[(3 * 4 + rb_j) * 33 + rb_b];
#pragma unroll
      for (int p = 0; p < 4; p++) {
        const float* qq = redb + p * 16 * 33 + rb_b;
        s0 += qq[(0 * 4 + rb_j) * 33];
        s1 += qq[(1 * 4 + rb_j) * 33];
        s2 += qq[(2 * 4 + rb_j) * 33];
        s3 += qq[(3 * 4 + rb_j) * 33];
      }
      float ig = fast_sig(s0);
      float fg = fast_sig(s1);
      float gg = fast_tanh(s2);
      float og = fast_sig(s3);
      c_reg = fg * c_reg + ig * gg;
      float h = og * fast_tanh(c_reg);
      // layout g_hs4[t][blk][b][4]: offset = rb_b*4 + rb_j  (BUG FIX: was +tid)
      g_hs4[((long)t * NB + blk) * (BATCH * 4) + rb_b * 4 + rb_j] = h;
      __syncwarp();
      if (lane == 0)
        asm volatile("red.release.gpu.global.add.u32 [%0], %1;"
                     :: "l"(&g_cnt16[(blk >> 3) * 64]), "r"(1u) : "memory");
    }
  }
}

// ---------------- phase 3: hs4[T][blk][b][4] -> out[B][H][T] ---------------
__global__ __launch_bounds__(256) void transpose_hs(float* __restrict__ out) {
  __shared__ float tile[32][33];
  const int t0 = blockIdx.x * 32, j0 = blockIdx.y * 32, b = blockIdx.z;
  const int tx = threadIdx.x, ty = threadIdx.y;
  for (int i = ty; i < 32; i += 8) {
    int j = j0 + tx;
    tile[i][tx] = g_hs4[(((long)(t0 + i) * NB + (j >> 2)) * BATCH + b) * 4 + (j & 3)];
  }
  __syncthreads();
  for (int i = ty; i < 32; i += 8)
    out[((long)b * HID + j0 + i) * T_LEN + t0 + tx] = tile[tx][i];
}

// ---------------- launch ----------------
extern "C" void kernel_launch(void* const* d_in, const int* in_sizes, int n_in,
                              void* d_out, int out_size) {
  (void)in_sizes; (void)n_in; (void)out_size;
  const float* x   = (const float*)d_in[0];
  const float* Wih = (const float*)d_in[1];
  const float* Whh = (const float*)d_in[2];
  const float* bih = (const float*)d_in[3];
  const float* bhh = (const float*)d_in[4];
  float* out = (float*)d_out;

  cudaFuncSetAttribute(lstm_scan, cudaFuncAttributeMaxDynamicSharedMemorySize,
                       SMEM_SCAN_BYTES);

  dim3 g1(T_LEN / 64, G4 / 64, BATCH);
  gemm_input<<<g1, 256>>>(x, Wih, bih, bhh);          // launch 1
  init_bar<<<1, 32>>>();                               // launch 2
  dummy_k<<<1, 32>>>();                                // launch 3
  lstm_scan<<<NB, NT, SMEM_SCAN_BYTES>>>(Whh);         // launch 4 (ncu window)

  dim3 g3(T_LEN / 32, HID / 32, BATCH);
  transpose_hs<<<g3, dim3(32, 8)>>>(out);              // launch 5
}

// round 9
// speedup vs baseline: 1.0008x; 1.0008x over previous
#include <cuda_runtime.h>
#include <math.h>
#include <stdint.h>

#define T_LEN 1024
#define BATCH 32
#define DIN   256
#define HID   512
#define G4    2048
#define NB    128
#define NT    512
#define BH    (BATCH*HID)

__device__ float g_gx[(long)T_LEN * BATCH * G4];          // [T][B][4H]
__device__ float g_hs4[(long)T_LEN * NB * BATCH * 4];     // [T][blk][b][4]
__device__ unsigned g_cnt16[1024];                        // counters at sg*64

// ---------------------------------------------------------------- helpers
__device__ __forceinline__ float fast_tanh(float x) {
  float y; asm("tanh.approx.f32 %0, %1;" : "=f"(y) : "f"(x)); return y;
}
__device__ __forceinline__ float fast_sig(float x) {
  return 0.5f * fast_tanh(0.5f * x) + 0.5f;
}
__device__ __forceinline__ void fma2(unsigned long long& d,
                                     unsigned long long a, unsigned long long b) {
  asm("fma.rn.f32x2 %0, %1, %2, %0;" : "+l"(d) : "l"(a), "l"(b));
}
__device__ __forceinline__ float hsum2(unsigned long long v) {
  return __uint_as_float((unsigned)v) + __uint_as_float((unsigned)(v >> 32));
}

// ---------------- phase 1: gx = x^T @ W_ih^T + (b_ih + b_hh) ----------------
__global__ __launch_bounds__(256) void gemm_input(
    const float* __restrict__ x, const float* __restrict__ Wih,
    const float* __restrict__ bih, const float* __restrict__ bhh) {
  __shared__ float xs[32][68];
  __shared__ float wsT[32][68];
  const int t0 = blockIdx.x * 64, n0 = blockIdx.y * 64, b = blockIdx.z;
  const int tid = threadIdx.x;
  const int tt4 = tid & 15, nn4 = tid >> 4;

  float acc[4][4];
#pragma unroll
  for (int i = 0; i < 4; i++)
#pragma unroll
    for (int j = 0; j < 4; j++) acc[i][j] = 0.f;

  for (int d0 = 0; d0 < DIN; d0 += 32) {
#pragma unroll
    for (int r = 0; r < 32; r += 4) {
      int dd = r + (tid >> 6);
      int tt = tid & 63;
      xs[dd][tt] = x[((long)b * DIN + d0 + dd) * T_LEN + t0 + tt];
    }
#pragma unroll
    for (int r = 0; r < 64; r += 8) {
      int nn = r + (tid >> 5);
      int dd = tid & 31;
      wsT[dd][nn] = Wih[(long)(n0 + nn) * DIN + d0 + dd];
    }
    __syncthreads();
#pragma unroll
    for (int dd = 0; dd < 32; dd++) {
      float4 a = *(const float4*)&xs[dd][tt4 * 4];
      float4 w = *(const float4*)&wsT[dd][nn4 * 4];
      acc[0][0] += a.x * w.x; acc[0][1] += a.x * w.y; acc[0][2] += a.x * w.z; acc[0][3] += a.x * w.w;
      acc[1][0] += a.y * w.x; acc[1][1] += a.y * w.y; acc[1][2] += a.y * w.z; acc[1][3] += a.y * w.w;
      acc[2][0] += a.z * w.x; acc[2][1] += a.z * w.y; acc[2][2] += a.z * w.z; acc[2][3] += a.z * w.w;
      acc[3][0] += a.w * w.x; acc[3][1] += a.w * w.y; acc[3][2] += a.w * w.z; acc[3][3] += a.w * w.w;
    }
    __syncthreads();
  }
  const int n = n0 + nn4 * 4;
  float4 b1 = *(const float4*)&bih[n];
  float4 b2 = *(const float4*)&bhh[n];
  float4 bv = make_float4(b1.x + b2.x, b1.y + b2.y, b1.z + b2.z, b1.w + b2.w);
#pragma unroll
  for (int i = 0; i < 4; i++) {
    int t = t0 + tt4 * 4 + i;
    float4 o = make_float4(acc[i][0] + bv.x, acc[i][1] + bv.y,
                           acc[i][2] + bv.z, acc[i][3] + bv.w);
    *(float4*)&g_gx[(long)t * (BATCH * G4) + (long)b * G4 + n] = o;
  }
}

__global__ void init_bar() {
  if (threadIdx.x < 16) *(volatile unsigned*)&g_cnt16[threadIdx.x * 64] = 0u;
}

__global__ void dummy_k() {}

// ---------------- phase 2: persistent recurrent scan (sub-chunk pipeline) ---
// 128 blocks x 512 threads. Block owns units j = blk*4+{0..3} (16 W rows in
// SMEM). Warp wid: q = wid>>2 (k-chunk), s = wid&3 (home sub-chunk);
// bh = wid&1, gh = (wid>>1)&1 select batch/gate halves for compute.
// h interchange: g_hs4[t][blk][b][4]; sub-chunk w = 8 producer blocks = 4KB,
// fetched by warp w's own cp.async.bulk gated by counter w (32 warp-arrivals)
// into hsm[w*1024], completion mbar[w]. Compute consumes sub-chunks of its
// chunk q in rotated order starting at its own s (order-independent accum).
#define KW      516
#define SM_W    (16 * KW)              // 8256
#define SM_H    (16 * 1024)            // 16384
#define SM_RED  (64 * 33)              // 2112 (x2 ping-pong)
#define SM_GXS  (16 * 33)              // 528  (x2 ping-pong)
#define SMEM_SCAN_FLOATS (SM_W + SM_H + 2 * SM_RED + 2 * SM_GXS + 40)
#define SMEM_SCAN_BYTES  (SMEM_SCAN_FLOATS * 4)

__global__ __launch_bounds__(NT, 1) void lstm_scan(const float* __restrict__ Whh) {
  extern __shared__ float sm[];
  float* Wsm  = sm;
  float* hsm  = Wsm + SM_W;
  float* red2 = hsm + SM_H;                 // [2][2112]
  float* gxs2 = red2 + 2 * SM_RED;          // [2][528]
  unsigned long long* mbar = (unsigned long long*)(gxs2 + 2 * SM_GXS);  // 16

  const int tid = threadIdx.x, blk = blockIdx.x;
  const int wid = tid >> 5, lane = tid & 31;
  const int bh = wid & 1, gh = (wid >> 1) & 1;
  const int q = wid >> 2, s = wid & 3;
  const int rsub = lane & 3, bsub = lane >> 2;
  const int r0 = gh * 8 + rsub * 2;
  const int b0 = bh * 16 + bsub * 2;
  const uint32_t mb_base = (uint32_t)__cvta_generic_to_shared(mbar);

  // persistent W_hh slice: row r = g*4+jj  <-  W_hh[g*512 + blk*4 + jj][:]
  for (int idx = tid; idx < 16 * HID; idx += NT) {
    int r = idx >> 9, k = idx & 511;
    int g = r >> 2, jj = r & 3;
    Wsm[r * KW + k] = Whh[(long)(g * HID + blk * 4 + jj) * HID + k];
  }
  for (int i = tid; i < SM_H; i += NT) hsm[i] = 0.f;
  if (tid < 16)
    asm volatile("mbarrier.init.shared.b64 [%0], 1;" :: "r"(mb_base + tid * 8));
  __syncthreads();

  const ulonglong2* w0p = (const ulonglong2*)(Wsm + r0 * KW + q * 128);
  const ulonglong2* w1p = (const ulonglong2*)(Wsm + (r0 + 1) * KW + q * 128);

  const int rb_j = tid >> 5, rb_b = tid & 31;   // reducer mapping (tid<128)
  float c_reg = 0.f;

  for (int t = 0; t < T_LEN; t++) {
    float* redb = red2 + (t & 1) * SM_RED;
    float* gxsb = gxs2 + (t & 1) * SM_GXS;

    // ---- gx prefetch (regs, independent of h) ----
    float4 gxv;
    if (tid < 128) {
      int b = tid >> 2, g = tid & 3;
      gxv = *(const float4*)&g_gx[(long)t * (BATCH * G4) + (long)b * G4 + g * HID + blk * 4];
    }

    // ---- sub-chunk fetch: every warp's lane 0 polls its own counter ----
    if (t > 0 && lane == 0) {
      const unsigned tgt = 32u * (unsigned)t;
      unsigned v;
      do {
        asm volatile("ld.acquire.gpu.global.u32 %0, [%1];"
                     : "=r"(v) : "l"(&g_cnt16[wid * 64]));
      } while (v < tgt);
      asm volatile("fence.proxy.async;" ::: "memory");
      uint32_t mb = mb_base + wid * 8;
      asm volatile("mbarrier.arrive.expect_tx.shared.b64 _, [%0], %1;"
                   :: "r"(mb), "r"(4096u));
      const float* src = g_hs4 + ((long)(t - 1) * NB + wid * 8) * (BATCH * 4);
      uint32_t d32 = (uint32_t)__cvta_generic_to_shared(hsm + wid * 1024);
      asm volatile(
        "cp.async.bulk.shared::cluster.global.mbarrier::complete_tx::bytes "
        "[%0], [%1], %2, [%3];"
        :: "r"(d32), "l"(src), "r"(4096u), "r"(mb) : "memory");
    }
    // gx -> smem transposed (ping-pong buffer)
    if (tid < 128) {
      int b = tid >> 2, g = tid & 3;
      gxsb[(g * 4 + 0) * 33 + b] = gxv.x;
      gxsb[(g * 4 + 1) * 33 + b] = gxv.y;
      gxsb[(g * 4 + 2) * 33 + b] = gxv.z;
      gxsb[(g * 4 + 3) * 33 + b] = gxv.w;
    }

    // ---- f32x2 GEMM partial over 4 sub-rounds (rotated, own sub first) ----
    unsigned long long a00 = 0ull, a01 = 0ull, a10 = 0ull, a11 = 0ull;
#pragma unroll
    for (int r = 0; r < 4; r++) {
      const int sr = (s + r) & 3;
      if (t > 0) {
        uint32_t mb = mb_base + (q * 4 + sr) * 8;
        uint32_t done = 0;
        unsigned phase = (unsigned)((t - 1) & 1);
        while (!done) {
          asm volatile(
            "{\n\t.reg .pred p;\n\t"
            "mbarrier.try_wait.parity.shared.b64 p, [%1], %2, 10000000;\n\t"
            "selp.b32 %0, 1, 0, p;\n\t}"
            : "=r"(done) : "r"(mb), "r"(phase) : "memory");
        }
      }
      const float* hb = hsm + (q * 4 + sr) * 1024 + b0 * 4;
#pragma unroll
      for (int i = 0; i < 8; i++) {
        ulonglong2 wa = w0p[sr * 8 + i];
        ulonglong2 wb = w1p[sr * 8 + i];
        ulonglong2 ha  = *(const ulonglong2*)(hb + i * 128);
        ulonglong2 hbv = *(const ulonglong2*)(hb + i * 128 + 4);
        fma2(a00, wa.x, ha.x);  fma2(a00, wa.y, ha.y);
        fma2(a01, wa.x, hbv.x); fma2(a01, wa.y, hbv.y);
        fma2(a10, wb.x, ha.x);  fma2(a10, wb.y, ha.y);
        fma2(a11, wb.x, hbv.x); fma2(a11, wb.y, hbv.y);
      }
    }
    {
      float* rp = redb + (q * 16 + r0) * 33;
      rp[b0]          = hsum2(a00);
      rp[b0 + 1]      = hsum2(a01);
      rp[33 + b0]     = hsum2(a10);
      rp[33 + b0 + 1] = hsum2(a11);
    }
    __syncthreads();

    // ---- reduce + gates (tid<128 owns (j = blk*4 + rb_j, b = rb_b)) ----
    if (tid < 128) {
      float s0 = gxsb[(0 * 4 + rb_j) * 33 + rb_b];
      float s1 = gxsb[(1 * 4 + rb_j) * 33 + rb_b];
      float s2 = gxsb[(2 * 4 + rb_j) * 33 + rb_b];
      float s3 = gxsb[(3 * 4 + rb_j) * 33 + rb_b];
#pragma unroll
      for (int p = 0; p < 4; p++) {
        const float* qq = redb + p * 16 * 33 + rb_b;
        s0 += qq[(0 * 4 + rb_j) * 33];
        s1 += qq[(1 * 4 + rb_j) * 33];
        s2 += qq[(2 * 4 + rb_j) * 33];
        s3 += qq[(3 * 4 + rb_j) * 33];
      }
      float ig = fast_sig(s0);
      float fg = fast_sig(s1);
      float gg = fast_tanh(s2);
      float og = fast_sig(s3);
      c_reg = fg * c_reg + ig * gg;
      float h = og * fast_tanh(c_reg);
      // layout g_hs4[t][blk][b][4]: offset = rb_b*4 + rb_j  (BUG FIX: was +tid)
      g_hs4[((long)t * NB + blk) * (BATCH * 4) + rb_b * 4 + rb_j] = h;
      __syncwarp();
      if (lane == 0)
        asm volatile("red.release.gpu.global.add.u32 [%0], %1;"
                     :: "l"(&g_cnt16[(blk >> 3) * 64]), "r"(1u) : "memory");
    }
  }
}

// ---------------- phase 3: hs4[T][blk][b][4] -> out[B][H][T] ---------------
__global__ __launch_bounds__(256) void transpose_hs(float* __restrict__ out) {
  __shared__ float tile[32][33];
  const int t0 = blockIdx.x * 32, j0 = blockIdx.y * 32, b = blockIdx.z;
  const int tx = threadIdx.x, ty = threadIdx.y;
  for (int i = ty; i < 32; i += 8) {
    int j = j0 + tx;
    tile[i][tx] = g_hs4[(((long)(t0 + i) * NB + (j >> 2)) * BATCH + b) * 4 + (j & 3)];
  }
  __syncthreads();
  for (int i = ty; i < 32; i += 8)
    out[((long)b * HID + j0 + i) * T_LEN + t0 + tx] = tile[tx][i];
}

// ---------------- launch ----------------
extern "C" void kernel_launch(void* const* d_in, const int* in_sizes, int n_in,
                              void* d_out, int out_size) {
  (void)in_sizes; (void)n_in; (void)out_size;
  const float* x   = (const float*)d_in[0];
  const float* Wih = (const float*)d_in[1];
  const float* Whh = (const float*)d_in[2];
  const float* bih = (const float*)d_in[3];
  const float* bhh = (const float*)d_in[4];
  float* out = (float*)d_out;

  cudaFuncSetAttribute(lstm_scan, cudaFuncAttributeMaxDynamicSharedMemorySize,
                       SMEM_SCAN_BYTES);

  dim3 g1(T_LEN / 64, G4 / 64, BATCH);
  gemm_input<<<g1, 256>>>(x, Wih, bih, bhh);          // launch 1
  init_bar<<<1, 32>>>();                               // launch 2
  dummy_k<<<1, 32>>>();                                // launch 3
  lstm_scan<<<NB, NT, SMEM_SCAN_BYTES>>>(Whh);         // launch 4 (ncu window)

  dim3 g3(T_LEN / 32, HID / 32, BATCH);
  transpose_hs<<<g3, dim3(32, 8)>>>(out);              // launch 5
}

// round 10
// speedup vs baseline: 1.0017x; 1.0009x over previous
#include <cuda_runtime.h>
#include <math.h>
#include <stdint.h>

#define T_LEN 1024
#define BATCH 32
#define DIN   256
#define HID   512
#define G4    2048
#define NB    128
#define NT    512
#define BH    (BATCH*HID)

__device__ float g_gx[(long)T_LEN * BATCH * G4];          // [T][B][4H]
__device__ float g_hs4[(long)T_LEN * NB * BATCH * 4];     // [T][blk][b][4]
__device__ unsigned g_cnt16[1024];                        // counters at sg*64

// ---------------------------------------------------------------- helpers
__device__ __forceinline__ float fast_tanh(float x) {
  float y; asm("tanh.approx.f32 %0, %1;" : "=f"(y) : "f"(x)); return y;
}
__device__ __forceinline__ float fast_sig(float x) {
  return 0.5f * fast_tanh(0.5f * x) + 0.5f;
}
__device__ __forceinline__ void fma2(unsigned long long& d,
                                     unsigned long long a, unsigned long long b) {
  asm("fma.rn.f32x2 %0, %1, %2, %0;" : "+l"(d) : "l"(a), "l"(b));
}
__device__ __forceinline__ float hsum2(unsigned long long v) {
  return __uint_as_float((unsigned)v) + __uint_as_float((unsigned)(v >> 32));
}

// ---------------- phase 1: gx = x^T @ W_ih^T + (b_ih + b_hh) ----------------
__global__ __launch_bounds__(256) void gemm_input(
    const float* __restrict__ x, const float* __restrict__ Wih,
    const float* __restrict__ bih, const float* __restrict__ bhh) {
  __shared__ float xs[32][68];
  __shared__ float wsT[32][68];
  const int t0 = blockIdx.x * 64, n0 = blockIdx.y * 64, b = blockIdx.z;
  const int tid = threadIdx.x;
  const int tt4 = tid & 15, nn4 = tid >> 4;

  float acc[4][4];
#pragma unroll
  for (int i = 0; i < 4; i++)
#pragma unroll
    for (int j = 0; j < 4; j++) acc[i][j] = 0.f;

  for (int d0 = 0; d0 < DIN; d0 += 32) {
#pragma unroll
    for (int r = 0; r < 32; r += 4) {
      int dd = r + (tid >> 6);
      int tt = tid & 63;
      xs[dd][tt] = x[((long)b * DIN + d0 + dd) * T_LEN + t0 + tt];
    }
#pragma unroll
    for (int r = 0; r < 64; r += 8) {
      int nn = r + (tid >> 5);
      int dd = tid & 31;
      wsT[dd][nn] = Wih[(long)(n0 + nn) * DIN + d0 + dd];
    }
    __syncthreads();
#pragma unroll
    for (int dd = 0; dd < 32; dd++) {
      float4 a = *(const float4*)&xs[dd][tt4 * 4];
      float4 w = *(const float4*)&wsT[dd][nn4 * 4];
      acc[0][0] += a.x * w.x; acc[0][1] += a.x * w.y; acc[0][2] += a.x * w.z; acc[0][3] += a.x * w.w;
      acc[1][0] += a.y * w.x; acc[1][1] += a.y * w.y; acc[1][2] += a.y * w.z; acc[1][3] += a.y * w.w;
      acc[2][0] += a.z * w.x; acc[2][1] += a.z * w.y; acc[2][2] += a.z * w.z; acc[2][3] += a.z * w.w;
      acc[3][0] += a.w * w.x; acc[3][1] += a.w * w.y; acc[3][2] += a.w * w.z; acc[3][3] += a.w * w.w;
    }
    __syncthreads();
  }
  const int n = n0 + nn4 * 4;
  float4 b1 = *(const float4*)&bih[n];
  float4 b2 = *(const float4*)&bhh[n];
  float4 bv = make_float4(b1.x + b2.x, b1.y + b2.y, b1.z + b2.z, b1.w + b2.w);
#pragma unroll
  for (int i = 0; i < 4; i++) {
    int t = t0 + tt4 * 4 + i;
    float4 o = make_float4(acc[i][0] + bv.x, acc[i][1] + bv.y,
                           acc[i][2] + bv.z, acc[i][3] + bv.w);
    *(float4*)&g_gx[(long)t * (BATCH * G4) + (long)b * G4 + n] = o;
  }
}

__global__ void init_bar() {
  if (threadIdx.x < 16) *(volatile unsigned*)&g_cnt16[threadIdx.x * 64] = 0u;
}

__global__ void dummy_k() {}

// ---------------- phase 2: persistent recurrent scan (sub-chunk pipeline) ---
// 128 blocks x 512 threads. Block owns units j = blk*4+{0..3} (16 W rows in
// SMEM). Warp wid: q = wid>>2 (k-chunk), s = wid&3 (home sub-chunk);
// bh = wid&1, gh = (wid>>1)&1 select batch/gate halves for compute.
// h interchange: g_hs4[t][blk][b][4]; sub-chunk w = 8 producer blocks = 4KB,
// fetched by warp w's own cp.async.bulk gated by counter w (32 warp-arrivals)
// into hsm[w*1024], completion mbar[w]. Compute consumes sub-chunks of its
// chunk q in rotated order starting at its own s (order-independent accum).
#define KW      516
#define SM_W    (16 * KW)              // 8256
#define SM_H    (16 * 1024)            // 16384
#define SM_RED  (64 * 33)              // 2112 (x2 ping-pong)
#define SM_GXS  (16 * 33)              // 528  (x2 ping-pong)
#define SMEM_SCAN_FLOATS (SM_W + SM_H + 2 * SM_RED + 2 * SM_GXS + 40)
#define SMEM_SCAN_BYTES  (SMEM_SCAN_FLOATS * 4)

__global__ __launch_bounds__(NT, 1) void lstm_scan(const float* __restrict__ Whh) {
  extern __shared__ float sm[];
  float* Wsm  = sm;
  float* hsm  = Wsm + SM_W;
  float* red2 = hsm + SM_H;                 // [2][2112]
  float* gxs2 = red2 + 2 * SM_RED;          // [2][528]
  unsigned long long* mbar = (unsigned long long*)(gxs2 + 2 * SM_GXS);  // 16

  const int tid = threadIdx.x, blk = blockIdx.x;
  const int wid = tid >> 5, lane = tid & 31;
  const int bh = wid & 1, gh = (wid >> 1) & 1;
  const int q = wid >> 2, s = wid & 3;
  const int rsub = lane & 3, bsub = lane >> 2;
  const int r0 = gh * 8 + rsub * 2;
  const int b0 = bh * 16 + bsub * 2;
  const uint32_t mb_base = (uint32_t)__cvta_generic_to_shared(mbar);

  // persistent W_hh slice: row r = g*4+jj  <-  W_hh[g*512 + blk*4 + jj][:]
  for (int idx = tid; idx < 16 * HID; idx += NT) {
    int r = idx >> 9, k = idx & 511;
    int g = r >> 2, jj = r & 3;
    Wsm[r * KW + k] = Whh[(long)(g * HID + blk * 4 + jj) * HID + k];
  }
  for (int i = tid; i < SM_H; i += NT) hsm[i] = 0.f;
  if (tid < 16)
    asm volatile("mbarrier.init.shared.b64 [%0], 1;" :: "r"(mb_base + tid * 8));
  __syncthreads();

  const ulonglong2* w0p = (const ulonglong2*)(Wsm + r0 * KW + q * 128);
  const ulonglong2* w1p = (const ulonglong2*)(Wsm + (r0 + 1) * KW + q * 128);

  const int rb_j = tid >> 5, rb_b = tid & 31;   // reducer mapping (tid<128)
  float c_reg = 0.f;

  for (int t = 0; t < T_LEN; t++) {
    float* redb = red2 + (t & 1) * SM_RED;
    float* gxsb = gxs2 + (t & 1) * SM_GXS;

    // ---- gx prefetch (regs, independent of h) ----
    float4 gxv;
    if (tid < 128) {
      int b = tid >> 2, g = tid & 3;
      gxv = *(const float4*)&g_gx[(long)t * (BATCH * G4) + (long)b * G4 + g * HID + blk * 4];
    }

    // ---- sub-chunk fetch: every warp's lane 0 polls its own counter ----
    if (t > 0 && lane == 0) {
      const unsigned tgt = 32u * (unsigned)t;
      unsigned v;
      do {
        asm volatile("ld.acquire.gpu.global.u32 %0, [%1];"
                     : "=r"(v) : "l"(&g_cnt16[wid * 64]));
      } while (v < tgt);
      asm volatile("fence.proxy.async;" ::: "memory");
      uint32_t mb = mb_base + wid * 8;
      asm volatile("mbarrier.arrive.expect_tx.shared.b64 _, [%0], %1;"
                   :: "r"(mb), "r"(4096u));
      const float* src = g_hs4 + ((long)(t - 1) * NB + wid * 8) * (BATCH * 4);
      uint32_t d32 = (uint32_t)__cvta_generic_to_shared(hsm + wid * 1024);
      asm volatile(
        "cp.async.bulk.shared::cluster.global.mbarrier::complete_tx::bytes "
        "[%0], [%1], %2, [%3];"
        :: "r"(d32), "l"(src), "r"(4096u), "r"(mb) : "memory");
    }
    // gx -> smem transposed (ping-pong buffer)
    if (tid < 128) {
      int b = tid >> 2, g = tid & 3;
      gxsb[(g * 4 + 0) * 33 + b] = gxv.x;
      gxsb[(g * 4 + 1) * 33 + b] = gxv.y;
      gxsb[(g * 4 + 2) * 33 + b] = gxv.z;
      gxsb[(g * 4 + 3) * 33 + b] = gxv.w;
    }

    // ---- f32x2 GEMM partial over 4 sub-rounds (rotated, own sub first) ----
    unsigned long long a00 = 0ull, a01 = 0ull, a10 = 0ull, a11 = 0ull;
#pragma unroll
    for (int r = 0; r < 4; r++) {
      const int sr = (s + r) & 3;
      if (t > 0) {
        uint32_t mb = mb_base + (q * 4 + sr) * 8;
        uint32_t done = 0;
        unsigned phase = (unsigned)((t - 1) & 1);
        while (!done) {
          asm volatile(
            "{\n\t.reg .pred p;\n\t"
            "mbarrier.try_wait.parity.shared.b64 p, [%1], %2, 10000000;\n\t"
            "selp.b32 %0, 1, 0, p;\n\t}"
            : "=r"(done) : "r"(mb), "r"(phase) : "memory");
        }
      }
      const float* hb = hsm + (q * 4 + sr) * 1024 + b0 * 4;
#pragma unroll
      for (int i = 0; i < 8; i++) {
        ulonglong2 wa = w0p[sr * 8 + i];
        ulonglong2 wb = w1p[sr * 8 + i];
        ulonglong2 ha  = *(const ulonglong2*)(hb + i * 128);
        ulonglong2 hbv = *(const ulonglong2*)(hb + i * 128 + 4);
        fma2(a00, wa.x, ha.x);  fma2(a00, wa.y, ha.y);
        fma2(a01, wa.x, hbv.x); fma2(a01, wa.y, hbv.y);
        fma2(a10, wb.x, ha.x);  fma2(a10, wb.y, ha.y);
        fma2(a11, wb.x, hbv.x); fma2(a11, wb.y, hbv.y);
      }
    }
    {
      float* rp = redb + (q * 16 + r0) * 33;
      rp[b0]          = hsum2(a00);
      rp[b0 + 1]      = hsum2(a01);
      rp[33 + b0]     = hsum2(a10);
      rp[33 + b0 + 1] = hsum2(a11);
    }
    __syncthreads();

    // ---- reduce + gates (tid<128 owns (j = blk*4 + rb_j, b = rb_b)) ----
    if (tid < 128) {
      float s0 = gxsb[(0 * 4 + rb_j) * 33 + rb_b];
      float s1 = gxsb[(1 * 4 + rb_j) * 33 + rb_b];
      float s2 = gxsb[(2 * 4 + rb_j) * 33 + rb_b];
      float s3 = gxsb[(3 * 4 + rb_j) * 33 + rb_b];
#pragma unroll
      for (int p = 0; p < 4; p++) {
        const float* qq = redb + p * 16 * 33 + rb_b;
        s0 += qq[(0 * 4 + rb_j) * 33];
        s1 += qq[(1 * 4 + rb_j) * 33];
        s2 += qq[(2 * 4 + rb_j) * 33];
        s3 += qq[(3 * 4 + rb_j) * 33];
      }
      float ig = fast_sig(s0);
      float fg = fast_sig(s1);
      float gg = fast_tanh(s2);
      float og = fast_sig(s3);
      c_reg = fg * c_reg + ig * gg;
      float h = og * fast_tanh(c_reg);
      // layout g_hs4[t][blk][b][4]: offset = rb_b*4 + rb_j  (BUG FIX: was +tid)
      g_hs4[((long)t * NB + blk) * (BATCH * 4) + rb_b * 4 + rb_j] = h;
      __syncwarp();
      if (lane == 0)
        asm volatile("red.release.gpu.global.add.u32 [%0], %1;"
                     :: "l"(&g_cnt16[(blk >> 3) * 64]), "r"(1u) : "memory");
    }
  }
}

// ---------------- phase 3: hs4[T][blk][b][4] -> out[B][H][T] ---------------
__global__ __launch_bounds__(256) void transpose_hs(float* __restrict__ out) {
  __shared__ float tile[32][33];
  const int t0 = blockIdx.x * 32, j0 = blockIdx.y * 32, b = blockIdx.z;
  const int tx = threadIdx.x, ty = threadIdx.y;
  for (int i = ty; i < 32; i += 8) {
    int j = j0 + tx;
    tile[i][tx] = g_hs4[(((long)(t0 + i) * NB + (j >> 2)) * BATCH + b) * 4 + (j & 3)];
  }
  __syncthreads();
  for (int i = ty; i < 32; i += 8)
    out[((long)b * HID + j0 + i) * T_LEN + t0 + tx] = tile[tx][i];
}

// ---------------- launch ----------------
extern "C" void kernel_launch(void* const* d_in, const int* in_sizes, int n_in,
                              void* d_out, int out_size) {
  (void)in_sizes; (void)n_in; (void)out_size;
  const float* x   = (const float*)d_in[0];
  const float* Wih = (const float*)d_in[1];
  const float* Whh = (const float*)d_in[2];
  const float* bih = (const float*)d_in[3];
  const float* bhh = (const float*)d_in[4];
  float* out = (float*)d_out;

  cudaFuncSetAttribute(lstm_scan, cudaFuncAttributeMaxDynamicSharedMemorySize,
                       SMEM_SCAN_BYTES);

  dim3 g1(T_LEN / 64, G4 / 64, BATCH);
  gemm_input<<<g1, 256>>>(x, Wih, bih, bhh);          // launch 1
  init_bar<<<1, 32>>>();                               // launch 2
  dummy_k<<<1, 32>>>();                                // launch 3
  lstm_scan<<<NB, NT, SMEM_SCAN_BYTES>>>(Whh);         // launch 4 (ncu window)

  dim3 g3(T_LEN / 32, HID / 32, BATCH);
  transpose_hs<<<g3, dim3(32, 8)>>>(out);              // launch 5
}

// round 11
// speedup vs baseline: 1.4567x; 1.4541x over previous
#include <cuda_runtime.h>
#include <math.h>
#include <stdint.h>

#define T_LEN 1024
#define BATCH 32
#define DIN   256
#define HID   512
#define G4    2048
#define NB    128
#define NT    512

__device__ float g_gx[(long)T_LEN * BATCH * G4];        // [T][B][4H]
__device__ float g_hs4[(long)T_LEN * NB * BATCH * 4];   // [T][k4=blk][b][4j]
__device__ unsigned g_cnt16[1024];                      // counters at w*64

// ---------------------------------------------------------------- helpers
__device__ __forceinline__ float fast_tanh(float x) {
  float y; asm("tanh.approx.f32 %0, %1;" : "=f"(y) : "f"(x)); return y;
}
__device__ __forceinline__ float fast_sig(float x) {
  return 0.5f * fast_tanh(0.5f * x) + 0.5f;
}
__device__ __forceinline__ void fma2(unsigned long long& d,
                                     unsigned long long a, unsigned long long b) {
  asm("fma.rn.f32x2 %0, %1, %2, %0;" : "+l"(d) : "l"(a), "l"(b));
}
__device__ __forceinline__ float hsum2(unsigned long long v) {
  return __uint_as_float((unsigned)v) + __uint_as_float((unsigned)(v >> 32));
}

// ---------------- phase 1: gx = x^T @ W_ih^T + (b_ih + b_hh) ----------------
__global__ __launch_bounds__(256) void gemm_input(
    const float* __restrict__ x, const float* __restrict__ Wih,
    const float* __restrict__ bih, const float* __restrict__ bhh) {
  __shared__ float xs[32][68];
  __shared__ float wsT[32][68];
  const int t0 = blockIdx.x * 64, n0 = blockIdx.y * 64, b = blockIdx.z;
  const int tid = threadIdx.x;
  const int tt4 = tid & 15, nn4 = tid >> 4;

  float acc[4][4];
#pragma unroll
  for (int i = 0; i < 4; i++)
#pragma unroll
    for (int j = 0; j < 4; j++) acc[i][j] = 0.f;

  for (int d0 = 0; d0 < DIN; d0 += 32) {
#pragma unroll
    for (int r = 0; r < 32; r += 4) {
      int dd = r + (tid >> 6);
      int tt = tid & 63;
      xs[dd][tt] = x[((long)b * DIN + d0 + dd) * T_LEN + t0 + tt];
    }
#pragma unroll
    for (int r = 0; r < 64; r += 8) {
      int nn = r + (tid >> 5);
      int dd = tid & 31;
      wsT[dd][nn] = Wih[(long)(n0 + nn) * DIN + d0 + dd];
    }
    __syncthreads();
#pragma unroll
    for (int dd = 0; dd < 32; dd++) {
      float4 a = *(const float4*)&xs[dd][tt4 * 4];
      float4 w = *(const float4*)&wsT[dd][nn4 * 4];
      acc[0][0] += a.x * w.x; acc[0][1] += a.x * w.y; acc[0][2] += a.x * w.z; acc[0][3] += a.x * w.w;
      acc[1][0] += a.y * w.x; acc[1][1] += a.y * w.y; acc[1][2] += a.y * w.z; acc[1][3] += a.y * w.w;
      acc[2][0] += a.z * w.x; acc[2][1] += a.z * w.y; acc[2][2] += a.z * w.z; acc[2][3] += a.z * w.w;
      acc[3][0] += a.w * w.x; acc[3][1] += a.w * w.y; acc[3][2] += a.w * w.z; acc[3][3] += a.w * w.w;
    }
    __syncthreads();
  }
  const int n = n0 + nn4 * 4;
  float4 b1 = *(const float4*)&bih[n];
  float4 b2 = *(const float4*)&bhh[n];
  float4 bv = make_float4(b1.x + b2.x, b1.y + b2.y, b1.z + b2.z, b1.w + b2.w);
#pragma unroll
  for (int i = 0; i < 4; i++) {
    int t = t0 + tt4 * 4 + i;
    float4 o = make_float4(acc[i][0] + bv.x, acc[i][1] + bv.y,
                           acc[i][2] + bv.z, acc[i][3] + bv.w);
    *(float4*)&g_gx[(long)t * (BATCH * G4) + (long)b * G4 + n] = o;
  }
}

__global__ void init_bar() {
  if (threadIdx.x < 16) *(volatile unsigned*)&g_cnt16[threadIdx.x * 64] = 0u;
}

__global__ void dummy_k() {}

// ---------------- phase 2: persistent recurrent scan ----------------
// 128 blocks x 512 threads. Block owns units j = blk*4+{0..3}: 16 W rows
// (r = g*4+jj) in SMEM (row stride KW=516). Warp wid = k-split (32 k each),
// k-range [wid*32, wid*32+32) -> needs h of producer blocks [wid*8, wid*8+8).
// Warp-private h staging: poll counter[wid] (8 producers x 4 warp-REDs = 32/t),
// then 8x LDG.128 (4KB contiguous) + 8x STS.128 into own SW128-swizzled
// region; __syncwarp; compute. No TMA/mbarrier. Lane = rg*8+bg; thread tile
// 4 rows x 4 batches x 32 k with 16 f32x2 accumulators.
#define KW      516
#define SM_W    (16 * KW)              // 8256
#define SM_H    (16 * 1024)            // 16384 (16 warp-regions of 4KB)
#define SM_RED  (256 * 33)             // 8448
#define SM_GXS  (16 * 33)              // 528
#define SMEM_SCAN_FLOATS (SM_W + SM_H + SM_RED + SM_GXS + 16)
#define SMEM_SCAN_BYTES  (SMEM_SCAN_FLOATS * 4)

__global__ __launch_bounds__(NT, 1) void lstm_scan(const float* __restrict__ Whh) {
  extern __shared__ float sm[];
  float* Wsm = sm;
  float* hsm = Wsm + SM_W;
  float* red = hsm + SM_H;
  float* gxs = red + SM_RED;

  const int tid = threadIdx.x, blk = blockIdx.x;
  const int wid = tid >> 5, lane = tid & 31;
  const int rg = lane >> 3, bg = lane & 7;

  // persistent W_hh slice: row r = g*4+jj  <-  W_hh[g*512 + blk*4 + jj][:]
  for (int idx = tid; idx < 16 * HID; idx += NT) {
    int r = idx >> 9, k = idx & 511;
    int g = r >> 2, jj = r & 3;
    Wsm[r * KW + k] = Whh[(long)(g * HID + blk * 4 + jj) * HID + k];
  }
  for (int i = tid; i < SM_H; i += NT) hsm[i] = 0.f;
  __syncthreads();

  // per-thread precomputed pointers/offsets
  const float* wp0 = Wsm + (rg * 4 + 0) * KW + wid * 32;
  const float* wp1 = Wsm + (rg * 4 + 1) * KW + wid * 32;
  const float* wp2 = Wsm + (rg * 4 + 2) * KW + wid * 32;
  const float* wp3 = Wsm + (rg * 4 + 3) * KW + wid * 32;
  float* hreg = hsm + wid * 1024;                // this warp's 4KB h region
  // swizzled word offsets: bx(b) = (b*4) ^ (((b>>3)&7)<<2)
  int bxw[4];
#pragma unroll
  for (int j = 0; j < 4; j++) {
    int b = bg * 4 + j;
    bxw[j] = (b * 4) ^ (((b >> 3) & 7) << 2);
  }
  const int bxl = (lane * 4) ^ (((lane >> 3) & 7) << 2);   // staging STS offset
  const int rb_j = tid >> 5, rb_b = tid & 31;              // reducers (tid<128)
  float c_reg = 0.f;

  for (int t = 0; t < T_LEN; t++) {
    // ---- gx prefetch (regs, independent of h) ----
    float4 gxv;
    if (tid < 128) {
      int b = tid >> 2, g = tid & 3;
      gxv = *(const float4*)&g_gx[(long)t * (BATCH * G4) + (long)b * G4 + g * HID + blk * 4];
    }

    // ---- warp-private h staging ----
    if (t > 0) {
      const unsigned tgt = 32u * (unsigned)t;
      unsigned v;
      do {
        asm volatile("ld.acquire.gpu.global.u32 %0, [%1];"
                     : "=r"(v) : "l"(&g_cnt16[wid * 64]) : "memory");
      } while (v < tgt);
      const float4* src = (const float4*)(g_hs4 + (long)(t - 1) * (NB * BATCH * 4))
                          + wid * 256;
      float4 s0 = src[0 * 32 + lane];
      float4 s1 = src[1 * 32 + lane];
      float4 s2 = src[2 * 32 + lane];
      float4 s3 = src[3 * 32 + lane];
      float4 s4 = src[4 * 32 + lane];
      float4 s5 = src[5 * 32 + lane];
      float4 s6 = src[6 * 32 + lane];
      float4 s7 = src[7 * 32 + lane];
      *(float4*)(hreg + 0 * 128 + (bxl ^ 0))  = s0;
      *(float4*)(hreg + 1 * 128 + (bxl ^ 16)) = s1;
      *(float4*)(hreg + 2 * 128 + (bxl ^ 0))  = s2;
      *(float4*)(hreg + 3 * 128 + (bxl ^ 16)) = s3;
      *(float4*)(hreg + 4 * 128 + (bxl ^ 0))  = s4;
      *(float4*)(hreg + 5 * 128 + (bxl ^ 16)) = s5;
      *(float4*)(hreg + 6 * 128 + (bxl ^ 0))  = s6;
      *(float4*)(hreg + 7 * 128 + (bxl ^ 16)) = s7;
      __syncwarp();
    }

    // gx -> smem transposed (writers == readers: reducer threads)
    if (tid < 128) {
      int b = tid >> 2, g = tid & 3;
      gxs[(g * 4 + 0) * 33 + b] = gxv.x;
      gxs[(g * 4 + 1) * 33 + b] = gxv.y;
      gxs[(g * 4 + 2) * 33 + b] = gxv.z;
      gxs[(g * 4 + 3) * 33 + b] = gxv.w;
    }

    // ---- f32x2 GEMM: 4 rows x 4 batches x 32 k ----
    unsigned long long acc[4][4];
#pragma unroll
    for (int m = 0; m < 4; m++)
#pragma unroll
      for (int j = 0; j < 4; j++) acc[m][j] = 0ull;

#pragma unroll
    for (int i = 0; i < 8; i++) {
      ulonglong2 w0 = *(const ulonglong2*)(wp0 + i * 4);
      ulonglong2 w1 = *(const ulonglong2*)(wp1 + i * 4);
      ulonglong2 w2 = *(const ulonglong2*)(wp2 + i * 4);
      ulonglong2 w3 = *(const ulonglong2*)(wp3 + i * 4);
      const int xm = (i & 1) << 4;
      ulonglong2 h0 = *(const ulonglong2*)(hreg + i * 128 + (bxw[0] ^ xm));
      ulonglong2 h1 = *(const ulonglong2*)(hreg + i * 128 + (bxw[1] ^ xm));
      ulonglong2 h2 = *(const ulonglong2*)(hreg + i * 128 + (bxw[2] ^ xm));
      ulonglong2 h3 = *(const ulonglong2*)(hreg + i * 128 + (bxw[3] ^ xm));
      fma2(acc[0][0], w0.x, h0.x); fma2(acc[0][0], w0.y, h0.y);
      fma2(acc[0][1], w0.x, h1.x); fma2(acc[0][1], w0.y, h1.y);
      fma2(acc[0][2], w0.x, h2.x); fma2(acc[0][2], w0.y, h2.y);
      fma2(acc[0][3], w0.x, h3.x); fma2(acc[0][3], w0.y, h3.y);
      fma2(acc[1][0], w1.x, h0.x); fma2(acc[1][0], w1.y, h0.y);
      fma2(acc[1][1], w1.x, h1.x); fma2(acc[1][1], w1.y, h1.y);
      fma2(acc[1][2], w1.x, h2.x); fma2(acc[1][2], w1.y, h2.y);
      fma2(acc[1][3], w1.x, h3.x); fma2(acc[1][3], w1.y, h3.y);
      fma2(acc[2][0], w2.x, h0.x); fma2(acc[2][0], w2.y, h0.y);
      fma2(acc[2][1], w2.x, h1.x); fma2(acc[2][1], w2.y, h1.y);
      fma2(acc[2][2], w2.x, h2.x); fma2(acc[2][2], w2.y, h2.y);
      fma2(acc[2][3], w2.x, h3.x); fma2(acc[2][3], w2.y, h3.y);
      fma2(acc[3][0], w3.x, h0.x); fma2(acc[3][0], w3.y, h0.y);
      fma2(acc[3][1], w3.x, h1.x); fma2(acc[3][1], w3.y, h1.y);
      fma2(acc[3][2], w3.x, h2.x); fma2(acc[3][2], w3.y, h2.y);
      fma2(acc[3][3], w3.x, h3.x); fma2(acc[3][3], w3.y, h3.y);
    }
    // ---- spill: row = wid*16 + rg*4 + m, col = bg*4 + (j^rg) (XOR swizzle)
#pragma unroll
    for (int m = 0; m < 4; m++) {
      float* rp = red + (wid * 16 + rg * 4 + m) * 33 + bg * 4;
#pragma unroll
      for (int j = 0; j < 4; j++) rp[j ^ rg] = hsum2(acc[m][j]);
    }
    __syncthreads();

    // ---- reduce + gates (tid<128 owns (j = blk*4 + rb_j, b = rb_b)) ----
    if (tid < 128) {
      float s[4];
#pragma unroll
      for (int g = 0; g < 4; g++) {
        float a = gxs[(g * 4 + rb_j) * 33 + rb_b];
        const int bsw = (rb_b & ~3) | ((rb_b & 3) ^ g);
#pragma unroll
        for (int ks = 0; ks < 16; ks++)
          a += red[(ks * 16 + g * 4 + rb_j) * 33 + bsw];
        s[g] = a;
      }
      float ig = fast_sig(s[0]);
      float fg = fast_sig(s[1]);
      float gg = fast_tanh(s[2]);
      float og = fast_sig(s[3]);
      c_reg = fg * c_reg + ig * gg;
      float h = og * fast_tanh(c_reg);
      g_hs4[((long)t * NB + blk) * (BATCH * 4) + rb_b * 4 + rb_j] = h;
      __syncwarp();
      if ((tid & 31) == 0)
        asm volatile("red.release.gpu.global.add.u32 [%0], %1;"
                     :: "l"(&g_cnt16[(blk >> 3) * 64]), "r"(1u) : "memory");
    }
    __syncthreads();   // protects red/gxs reuse at t+1
  }
}

// ---------------- phase 3: hs4[T][k4][b][4] -> out[B][H][T] ---------------
__global__ __launch_bounds__(256) void transpose_hs(float* __restrict__ out) {
  __shared__ float tile[32][33];
  const int t0 = blockIdx.x * 32, j0 = blockIdx.y * 32, b = blockIdx.z;
  const int tx = threadIdx.x, ty = threadIdx.y;
  for (int i = ty; i < 32; i += 8) {
    int j = j0 + tx;
    tile[i][tx] = g_hs4[(((long)(t0 + i) * NB + (j >> 2)) * BATCH + b) * 4 + (j & 3)];
  }
  __syncthreads();
  for (int i = ty; i < 32; i += 8)
    out[((long)b * HID + j0 + i) * T_LEN + t0 + tx] = tile[tx][i];
}

// ---------------- launch ----------------
extern "C" void kernel_launch(void* const* d_in, const int* in_sizes, int n_in,
                              void* d_out, int out_size) {
  (void)in_sizes; (void)n_in; (void)out_size;
  const float* x   = (const float*)d_in[0];
  const float* Wih = (const float*)d_in[1];
  const float* Whh = (const float*)d_in[2];
  const float* bih = (const float*)d_in[3];
  const float* bhh = (const float*)d_in[4];
  float* out = (float*)d_out;

  cudaFuncSetAttribute(lstm_scan, cudaFuncAttributeMaxDynamicSharedMemorySize,
                       SMEM_SCAN_BYTES);

  dim3 g1(T_LEN / 64, G4 / 64, BATCH);
  gemm_input<<<g1, 256>>>(x, Wih, bih, bhh);          // launch 1
  init_bar<<<1, 32>>>();                               // launch 2
  dummy_k<<<1, 32>>>();                                // launch 3
  lstm_scan<<<NB, NT, SMEM_SCAN_BYTES>>>(Whh);         // launch 4 (ncu window)

  dim3 g3(T_LEN / 32, HID / 32, BATCH);
  transpose_hs<<<g3, dim3(32, 8)>>>(out);              // launch 5
}